// round 5
// baseline (speedup 1.0000x reference)
#include <cuda_runtime.h>

// EEG_SimpleLSM: 3-layer LIF winner-take-all liquid state machine.
// x: [256, 32, 4000] f32, W1: [64,32], W2: [128,64]. Output: exp(pre_v2@T-1) [256,128].
//
// Structure = round-3 winner (software-pipelined across layers, one warp per
// sample, 256x32 launch): L2(t) / L1(t+1) / L0(t+2) are mutually independent
// inside one iteration, so their REDUX chains and gathers overlap; only the
// short per-layer v recurrences are serial.
//
// ROUND 5: packed f32x2 arithmetic (FFMA2/FMUL2 via PTX — ptxas never emits
// these from scalar C++). L1 packs its 2 membranes/lane, L2 packs 4 as two
// pairs: Markstein constant-division, charge fma and subtract all run at
// 2 elems/slot. Per-lane rounding of f32x2 is RN, and (vh - d) is computed
// as fma(d, -1, vh) = RN(vh - d) -> bit-identical to the scalar sequence
// (rel_err must remain exactly 4.882994e-08).

#define NB   256
#define NCH  32
#define NT   4000

typedef unsigned long long u64;

__device__ __align__(16) float g_W1T[32 * 64];   // W1T[c][j] = W1[j][c]
__device__ __align__(16) float g_W2T[64 * 128];  // W2T[c][j] = W2[j][c]

__global__ void prep_kernel(const float* __restrict__ W1, const float* __restrict__ W2) {
    int tid = blockIdx.x * blockDim.x + threadIdx.x;
    int nthr = blockDim.x * gridDim.x;
    for (int i = tid; i < 64 * 32; i += nthr) {
        int r = i >> 5, c = i & 31;
        g_W1T[c * 64 + r] = W1[i];
    }
    for (int i = tid; i < 128 * 64; i += nthr) {
        int r = i >> 6, c = i & 63;
        g_W2T[c * 128 + r] = W2[i];
    }
}

// ---- packed f32x2 helpers ----
__device__ __forceinline__ u64 pk2(float lo, float hi) {
    u64 r; asm("mov.b64 %0, {%1, %2};" : "=l"(r) : "f"(lo), "f"(hi)); return r;
}
__device__ __forceinline__ void upk2(u64 p, float& lo, float& hi) {
    asm("mov.b64 {%0, %1}, %2;" : "=f"(lo), "=f"(hi) : "l"(p));
}
__device__ __forceinline__ u64 mul2(u64 a, u64 b) {
    u64 r; asm("mul.rn.f32x2 %0, %1, %2;" : "=l"(r) : "l"(a), "l"(b)); return r;
}
__device__ __forceinline__ u64 fma2(u64 a, u64 b, u64 c) {
    u64 r; asm("fma.rn.f32x2 %0, %1, %2, %3;" : "=l"(r) : "l"(a), "l"(b), "l"(c)); return r;
}

// Correctly-rounded division by constant c (rc = RN(1/c)), Markstein sequence.
__device__ __forceinline__ float divc(float v, float c, float rc) {
    float q = v * rc;
    float r = __fmaf_rn(-c, q, v);
    return __fmaf_rn(r, rc, q);
}

// Packed Markstein: per-lane identical to divc.
__device__ __forceinline__ u64 divc2(u64 v, u64 nc2, u64 rc2) {
    u64 q = mul2(v, rc2);
    u64 r = fma2(nc2, q, v);
    return fma2(r, rc2, q);
}

// Monotone key: strictly order-preserving float -> unsigned mapping.
__device__ __forceinline__ unsigned fkey(float v) {
    unsigned b = __float_as_uint(v);
    return b ^ ((unsigned)((int)b >> 31) | 0x80000000u);
}

// key(1.5f): 0x3FC00000 -> 0xBFC00000 ; key(1.2f): 0x3F99999A -> 0xBF99999A
#define KEY_VTH0 0xBFC00000u
#define KEY_VTH1 0xBF99999Au

__global__ void __launch_bounds__(32)
lsm_kernel(const float* __restrict__ x, float* __restrict__ out) {
    const int b    = blockIdx.x;
    const int lane = threadIdx.x;

    const float RCT = 1.0f / 80000.0f;
    // Packed constants (hoisted)
    const u64 RCT2  = pk2(RCT, RCT);
    const u64 NTAU2 = pk2(-80000.0f, -80000.0f);
    const u64 NEG12 = pk2(-1.0f, -1.0f);

    // Per-lane state: lane l owns v0[l], v1[2l..2l+1], v2[4l..4l+3]
    float v0  = 0.0f;
    float v1a = 0.0f, v1b = 0.0f;
    float4 v2 = make_float4(0.f, 0.f, 0.f, 0.f);
    float4 pc = make_float4(0.f, 0.f, 0.f, 0.f);

    // Pipeline tokens (zero tokens: first L1/L2 executions are exact no-ops)
    float    s0_d = 0.0f;  unsigned idx0_d = 0u;
    float    s1_d = 0.0f;  unsigned idx1_d = 0u;

    const float4* xp  = reinterpret_cast<const float4*>(x + (size_t)b * (NCH * NT) + lane * NT);
    const float2* w1p = reinterpret_cast<const float2*>(g_W1T);
    const float4* w2p = reinterpret_cast<const float4*>(g_W2T);

    float4 c0 = __ldg(xp + 0);
    float4 c1 = __ldg(xp + 1);

    const int NBLK = NT / 8;  // 500
    for (int blk = 0; blk < NBLK + 1; ++blk) {
        float xs[8];
        float4 n0, n1;
        bool main_iter = (blk < NBLK);
        if (main_iter) {
            int nb = (blk + 1 < NBLK) ? (blk + 1) * 2 : 0;
            n0 = __ldg(xp + nb);
            n1 = __ldg(xp + nb + 1);
            xs[0]=c0.x; xs[1]=c0.y; xs[2]=c0.z; xs[3]=c0.w;
            xs[4]=c1.x; xs[5]=c1.y; xs[6]=c1.z; xs[7]=c1.w;
        }
        // Last pass (blk == NBLK): drain 2 remaining pipeline steps
        const int nsteps = main_iter ? 8 : 2;

#pragma unroll 8
        for (int j = 0; j < nsteps; ++j) {
            // ---- L2 at step t (consumes last iteration's (s1,idx1)) ----
            {
                float4 w2 = __ldg(w2p + (idx1_d << 5) + lane);  // W2T[idx1][4l..4l+3]
                u64 vxy = pk2(v2.x, v2.y);
                u64 vzw = pk2(v2.z, v2.w);
                u64 dxy = divc2(vxy, NTAU2, RCT2);
                u64 dzw = divc2(vzw, NTAU2, RCT2);
                u64 s1p = pk2(s1_d, s1_d);
                u64 pxy = fma2(dxy, NEG12, fma2(pk2(w2.x, w2.y), s1p, vxy));
                u64 pzw = fma2(dzw, NEG12, fma2(pk2(w2.z, w2.w), s1p, vzw));
                upk2(pxy, pc.x, pc.y);
                upk2(pzw, pc.z, pc.w);
                v2.x = (pc.x >= 1.2f) ? 0.0f : pc.x;
                v2.y = (pc.y >= 1.2f) ? 0.0f : pc.y;
                v2.z = (pc.z >= 1.2f) ? 0.0f : pc.z;
                v2.w = (pc.w >= 1.2f) ? 0.0f : pc.w;
            }
            // ---- L1 at step t+1 (consumes last iteration's (s0,idx0)) ----
            {
                float2 w1 = __ldg(w1p + (idx0_d << 5) + lane);  // W1T[idx0][2l..2l+1]
                u64 v1p = pk2(v1a, v1b);
                u64 d   = divc2(v1p, NTAU2, RCT2);
                u64 s0p = pk2(s0_d, s0_d);
                u64 ch  = fma2(d, NEG12, fma2(pk2(w1.x, w1.y), s0p, v1p));
                float cha, chb;
                upk2(ch, cha, chb);

                unsigned ka = fkey(cha);
                unsigned kb = fkey(chb);
                bool bw = kb > ka;
                unsigned lk = bw ? kb : ka;
                unsigned li = 2u * (unsigned)lane + (bw ? 1u : 0u);
                unsigned m1   = __reduce_max_sync(0xFFFFFFFFu, lk);
                unsigned cand = (lk == m1) ? li : 64u;
                idx1_d = __reduce_min_sync(0xFFFFFFFFu, cand);
                s1_d   = (m1 >= KEY_VTH1) ? 1.0f : 0.0f;

                v1a = (cha >= 1.2f) ? 0.0f : cha;
                v1b = (chb >= 1.2f) ? 0.0f : chb;
            }
            // ---- L0 at step t+2 (produces fresh (s0,idx0)) ----
            if (main_iter) {
                float d0  = divc(v0, 3.0f, 1.0f / 3.0f);
                float ch0 = (v0 + xs[j]) - d0;
                unsigned k0   = fkey(ch0);
                unsigned m0   = __reduce_max_sync(0xFFFFFFFFu, k0);
                unsigned cand = (k0 == m0) ? (unsigned)lane : 32u;
                idx0_d = __reduce_min_sync(0xFFFFFFFFu, cand);
                s0_d   = (m0 >= KEY_VTH0) ? 1.0f : 0.0f;
                v0 = (ch0 >= 1.5f) ? 0.0f : ch0;
            }
        }

        c0 = n0;
        c1 = n1;
    }

    // liquid state: exp of last-step pre-reset v2
    float4 o;
    o.x = expf(pc.x);
    o.y = expf(pc.y);
    o.z = expf(pc.z);
    o.w = expf(pc.w);
    reinterpret_cast<float4*>(out + (size_t)b * 128)[lane] = o;
}

extern "C" void kernel_launch(void* const* d_in, const int* in_sizes, int n_in,
                              void* d_out, int out_size) {
    const float* x  = (const float*)d_in[0];
    const float* W1 = (const float*)d_in[1];
    const float* W2 = (const float*)d_in[2];
    float* out = (float*)d_out;

    prep_kernel<<<1, 256>>>(W1, W2);
    lsm_kernel<<<NB, 32>>>(x, out);
}